// round 8
// baseline (speedup 1.0000x reference)
#include <cuda_runtime.h>
#include <cstdint>

// Fused 3-stage Tucker transform, bf16 two-plane split on m16n8k16 mma.sync.
// Per CTA = one batch tile of 32*32*32 fp32 in smem (fp32 master copy).
// Stage GEMM: out[m,i] = sum_c A[m,c] * w[c,i], M=1024, N=32, K=32.
// Split: v = b0 + b1 (bf16 planes); product = b0*B0 + b0*B1 + b1*B0.
// Smem layout uses sidx(r,c) bank bijection: fill, A-fragment loads (k-cols
// at stride 2), transposed epilogue stores (with lane-parity interleave of
// the +0/+1 row pair), and packed-weight loads are all bank-conflict-free.

#define NT 1024
#define S_WORDS 32768                    // 1024 rows x 32 cols fp32
#define WPL 640                          // weight plane: 32 rows x 20 words
#define SMEM_BYTES ((S_WORDS + 6 * WPL) * 4)   // 146432

__device__ __forceinline__ int sidx(int r, int c) {
    int p0  = (c ^ r) & 1;
    int p12 = ((c >> 1) + (r >> 1)) & 3;
    int p34 = ((c >> 3) + (r >> 1) + (r >> 3) + (r >> 6)) & 3;
    return (r << 5) | p0 | (p12 << 1) | (p34 << 3);
}

__device__ __forceinline__ uint32_t packbf(float hi, float lo) {
    uint32_t r;
    asm("cvt.rn.bf16x2.f32 %0, %1, %2;" : "=r"(r) : "f"(hi), "f"(lo));
    return r;
}

// v = plane0 + plane1: u = bf16x2(vhi, vlo); residual packed likewise.
__device__ __forceinline__ void split2(float vhi, float vlo, uint32_t& u, uint32_t& w) {
    u = packbf(vhi, vlo);
    float rlo = vlo - __uint_as_float(u << 16);
    float rhi = vhi - __uint_as_float(u & 0xFFFF0000u);
    w = packbf(rhi, rlo);
}

__device__ __forceinline__ void mma16(float* d, const uint32_t* a, uint32_t b0, uint32_t b1) {
    asm volatile(
        "mma.sync.aligned.m16n8k16.row.col.f32.bf16.bf16.f32 "
        "{%0,%1,%2,%3}, {%4,%5,%6,%7}, {%8,%9}, {%0,%1,%2,%3};"
        : "+f"(d[0]), "+f"(d[1]), "+f"(d[2]), "+f"(d[3])
        : "r"(a[0]), "r"(a[1]), "r"(a[2]), "r"(a[3]), "r"(b0), "r"(b1));
}

__global__ __launch_bounds__(NT, 1)
void tucker3_bf16(const float* __restrict__ x,
                  const float* __restrict__ w0,
                  const float* __restrict__ w1,
                  const float* __restrict__ w2,
                  float* __restrict__ out)
{
    extern __shared__ float smem[];
    float* S = smem;
    uint32_t* WB = (uint32_t*)(smem + S_WORDS);   // [stage*2+plane][i*20 + c2]

    const int tid  = threadIdx.x;
    const int wid  = tid >> 5;
    const int lane = tid & 31;
    const int g    = lane >> 2;    // 0..7
    const int tig  = lane & 3;     // 0..3
    const long base = (long)blockIdx.x << 15;

    // ---- Weight prep: pack consecutive-c bf16 pairs, two planes, 3 stages.
    if (tid < 512) {
        int i = tid & 31, c2 = tid >> 5;          // c2 = 0..15 (k-pair index)
        int gl = (2 * c2) * 32 + i, gh = gl + 32;
        int wo = i * 20 + c2;
        uint32_t p, q;
        { float a = w0[gl], b = w0[gh]; split2(b, a, p, q);
          WB[wo] = p; WB[WPL + wo] = q; }
        { float a = w1[gl], b = w1[gh]; split2(b, a, p, q);
          WB[2 * WPL + wo] = p; WB[3 * WPL + wo] = q; }
        { float a = w2[gl], b = w2[gh]; split2(b, a, p, q);
          WB[4 * WPL + wo] = p; WB[5 * WPL + wo] = q; }
    }

    // ---- Stage-0 fill: A[m][c] = x[c*1024 + m], coalesced gmem reads.
    {
        const float* xb = x + base;
        #pragma unroll 4
        for (int j = 0; j < 32; j++)
            S[sidx(tid, j)] = xb[(j << 10) + tid];
    }
    __syncthreads();

    #pragma unroll 1
    for (int s = 0; s < 3; s++) {
        const uint32_t* Wp0 = WB + 2 * s * WPL;
        const uint32_t* Wp1 = Wp0 + WPL;

        float acc[2][4][4];
        #pragma unroll
        for (int a = 0; a < 2; a++)
            #pragma unroll
            for (int b = 0; b < 4; b++)
                #pragma unroll
                for (int q = 0; q < 4; q++)
                    acc[a][b][q] = 0.0f;

        #pragma unroll
        for (int ks = 0; ks < 2; ks++) {          // two k16 chunks
            uint32_t ua[2][4], va[2][4];
            #pragma unroll
            for (int st = 0; st < 2; st++) {
                int r0 = (wid << 5) + (st << 4) + g;
                int r1 = r0 + 8;
                int c0 = (ks << 4) + (tig << 1);
                float v00 = S[sidx(r0, c0)],     v01 = S[sidx(r0, c0 + 1)];
                float v10 = S[sidx(r1, c0)],     v11 = S[sidx(r1, c0 + 1)];
                float v02 = S[sidx(r0, c0 + 8)], v03 = S[sidx(r0, c0 + 9)];
                float v12 = S[sidx(r1, c0 + 8)], v13 = S[sidx(r1, c0 + 9)];
                split2(v01, v00, ua[st][0], va[st][0]);
                split2(v11, v10, ua[st][1], va[st][1]);
                split2(v03, v02, ua[st][2], va[st][2]);
                split2(v13, v12, ua[st][3], va[st][3]);
            }
            #pragma unroll
            for (int nt = 0; nt < 4; nt++) {
                int wb = (nt * 8 + g) * 20 + (ks << 3) + tig;
                uint32_t b00 = Wp0[wb], b01 = Wp0[wb + 4];
                uint32_t b10 = Wp1[wb], b11 = Wp1[wb + 4];
                // 6 MMAs alternate st -> no back-to-back RAW on one acc.
                mma16(acc[0][nt], ua[0], b00, b01);   // b0*B0
                mma16(acc[1][nt], ua[1], b00, b01);
                mma16(acc[0][nt], ua[0], b10, b11);   // b0*B1
                mma16(acc[1][nt], ua[1], b10, b11);
                mma16(acc[0][nt], va[0], b00, b01);   // b1*B0
                mma16(acc[1][nt], va[1], b00, b01);
            }
        }

        __syncthreads();   // all reads of S for this stage complete

        if (s < 2) {
            // out[m][i] -> next A row r' = (m&31)*32 + i, col c' = wid.
            // Lane-parity interleave of the (r', r'+1) pair stores.
            const int godd = g & 1;
            const int doff = 32 + 1 - 2 * (wid & 1);   // addr(r'+1) - addr(r')
            #pragma unroll
            for (int st = 0; st < 2; st++)
                #pragma unroll
                for (int nt = 0; nt < 4; nt++) {
                    const int i0 = (nt << 3) + (tig << 1);
                    #pragma unroll
                    for (int mh = 0; mh < 2; mh++) {
                        int mloc = (st << 4) + (mh << 3) + g;
                        int ad = sidx((mloc << 5) + i0, wid);
                        float vA = godd ? acc[st][nt][2 * mh + 1] : acc[st][nt][2 * mh];
                        float vB = godd ? acc[st][nt][2 * mh]     : acc[st][nt][2 * mh + 1];
                        S[ad + godd * doff]          = vA;
                        S[ad + doff - godd * doff]   = vB;
                    }
                }
            __syncthreads();
        } else {
            // Final stage: straight to gmem, out flat = m*32 + i.
            float* ob = out + base;
            #pragma unroll
            for (int st = 0; st < 2; st++)
                #pragma unroll
                for (int nt = 0; nt < 4; nt++) {
                    const int m0 = (wid << 5) + (st << 4) + g;
                    const int m1 = m0 + 8;
                    const int i0 = (nt << 3) + (tig << 1);
                    *(float2*)&ob[(m0 << 5) + i0] =
                        make_float2(acc[st][nt][0], acc[st][nt][1]);
                    *(float2*)&ob[(m1 << 5) + i0] =
                        make_float2(acc[st][nt][2], acc[st][nt][3]);
                }
        }
    }
}

extern "C" void kernel_launch(void* const* d_in, const int* in_sizes, int n_in,
                              void* d_out, int out_size)
{
    const float* x  = (const float*)d_in[0];
    const float* w0 = (const float*)d_in[1];
    const float* w1 = (const float*)d_in[2];
    const float* w2 = (const float*)d_in[3];
    float* out = (float*)d_out;

    const int nBatch = in_sizes[0] >> 15;

    cudaFuncSetAttribute(tucker3_bf16,
                         cudaFuncAttributeMaxDynamicSharedMemorySize, SMEM_BYTES);
    tucker3_bf16<<<nBatch, NT, SMEM_BYTES>>>(x, w0, w1, w2, out);
}

// round 9
// speedup vs baseline: 1.1729x; 1.1729x over previous
#include <cuda_runtime.h>
#include <cstdint>

// Fused-through-gmem 3-stage Tucker transform: three independent streaming
// GEMM launches. Stage s: out[b, m*32+i] = sum_c in[b, c*1024+m] * w_s[c,i],
// b<1024, m<1024, c,i<32. Chain: x -> d_out -> scratch -> d_out.
// Numerics: bf16 two-plane split on mma.sync m16n8k16 (b0*B0 + b0*B1 + b1*B0),
// verified rel_err ~7.6e-6 in the fused variant.
// CTA = 256 threads, one (b, 256-row m-block): smem A tile 32x256 fp32
// (stride 260 -> all fragment LDS bank-conflict-free), weights pre-split
// into two bf16x2 planes (stride 20 -> conflict-free).

#define MBLK 256
#define AST  260                      // A tile row stride (words)

__device__ float g_scratch[32 * 1024 * 1024];   // 128 MB inter-stage buffer

__device__ __forceinline__ uint32_t packbf(float hi, float lo) {
    uint32_t r;
    asm("cvt.rn.bf16x2.f32 %0, %1, %2;" : "=r"(r) : "f"(hi), "f"(lo));
    return r;
}

// v = plane0 + plane1 per lane; u = bf16x2(hi,lo), w = residual bf16x2.
__device__ __forceinline__ void split2(float vhi, float vlo, uint32_t& u, uint32_t& w) {
    u = packbf(vhi, vlo);
    float rlo = vlo - __uint_as_float(u << 16);
    float rhi = vhi - __uint_as_float(u & 0xFFFF0000u);
    w = packbf(rhi, rlo);
}

__device__ __forceinline__ void mma16(float* d, const uint32_t* a, uint32_t b0, uint32_t b1) {
    asm volatile(
        "mma.sync.aligned.m16n8k16.row.col.f32.bf16.bf16.f32 "
        "{%0,%1,%2,%3}, {%4,%5,%6,%7}, {%8,%9}, {%0,%1,%2,%3};"
        : "+f"(d[0]), "+f"(d[1]), "+f"(d[2]), "+f"(d[3])
        : "r"(a[0]), "r"(a[1]), "r"(a[2]), "r"(a[3]), "r"(b0), "r"(b1));
}

__global__ __launch_bounds__(256)
void stage_kernel(const float* __restrict__ in,
                  const float* __restrict__ w,
                  float* __restrict__ out)
{
    __shared__ float    Sa[32 * AST];       // [c][m], 33280 B
    __shared__ uint32_t Wb[2][640];         // [plane][n*20 + k2], 5120 B

    const int tid  = threadIdx.x;
    const int wid  = tid >> 5;
    const int lane = tid & 31;
    const int g    = lane >> 2;
    const int tig  = lane & 3;

    const int b  = blockIdx.x >> 2;
    const int mb = (blockIdx.x & 3) << 8;
    const long bb = (long)b << 15;

    // ---- Weight prep: split w into two bf16x2 planes (k-pairs packed). ----
    #pragma unroll
    for (int e = tid; e < 512; e += 256) {
        int n = e & 31, k2 = e >> 5;                 // k2 = 0..15
        float lo = w[(2 * k2) * 32 + n];
        float hi = w[(2 * k2 + 1) * 32 + n];
        uint32_t p, q;
        split2(hi, lo, p, q);
        Wb[0][n * 20 + k2] = p;
        Wb[1][n * 20 + k2] = q;
    }

    // ---- A tile: Sa[c][m] = in[b, c*1024 + mb + m], coalesced rows. ----
    {
        const float* inb = in + bb + mb;
        #pragma unroll 8
        for (int c = 0; c < 32; c++)
            Sa[c * AST + tid] = inb[c * 1024 + tid];
    }
    __syncthreads();

    // ---- Mainloop: per warp 32 m-rows (2 m16 strips), N=32, K=32. ----
    float acc[2][4][4];
    #pragma unroll
    for (int a = 0; a < 2; a++)
        #pragma unroll
        for (int n = 0; n < 4; n++)
            #pragma unroll
            for (int q = 0; q < 4; q++)
                acc[a][n][q] = 0.0f;

    #pragma unroll
    for (int ks = 0; ks < 2; ks++) {
        uint32_t ua[2][4], va[2][4];
        #pragma unroll
        for (int st = 0; st < 2; st++) {
            int m0 = (wid << 5) + (st << 4) + g;
            int m1 = m0 + 8;
            int c0 = (ks << 4) + (tig << 1);
            float v00 = Sa[c0 * AST + m0],       v01 = Sa[(c0 + 1) * AST + m0];
            float v10 = Sa[c0 * AST + m1],       v11 = Sa[(c0 + 1) * AST + m1];
            float v02 = Sa[(c0 + 8) * AST + m0], v03 = Sa[(c0 + 9) * AST + m0];
            float v12 = Sa[(c0 + 8) * AST + m1], v13 = Sa[(c0 + 9) * AST + m1];
            split2(v01, v00, ua[st][0], va[st][0]);
            split2(v11, v10, ua[st][1], va[st][1]);
            split2(v03, v02, ua[st][2], va[st][2]);
            split2(v13, v12, ua[st][3], va[st][3]);
        }
        #pragma unroll
        for (int nt = 0; nt < 4; nt++) {
            int wo = (nt * 8 + g) * 20 + (ks << 3) + tig;
            uint32_t b00 = Wb[0][wo], b01 = Wb[0][wo + 4];
            uint32_t b10 = Wb[1][wo], b11 = Wb[1][wo + 4];
            mma16(acc[0][nt], ua[0], b00, b01);   // b0*B0
            mma16(acc[1][nt], ua[1], b00, b01);
            mma16(acc[0][nt], ua[0], b10, b11);   // b0*B1
            mma16(acc[1][nt], ua[1], b10, b11);
            mma16(acc[0][nt], va[0], b00, b01);   // b1*B0
            mma16(acc[1][nt], va[1], b00, b01);
        }
    }

    // ---- Epilogue: out[b, (mb+m)*32 + i], float2 per (row, n-tile). ----
    {
        float* ob = out + bb + (long)mb * 32;
        #pragma unroll
        for (int st = 0; st < 2; st++) {
            int m0 = (wid << 5) + (st << 4) + g;
            int m1 = m0 + 8;
            #pragma unroll
            for (int nt = 0; nt < 4; nt++) {
                int i0 = (nt << 3) + (tig << 1);
                *(float2*)&ob[(m0 << 5) + i0] =
                    make_float2(acc[st][nt][0], acc[st][nt][1]);
                *(float2*)&ob[(m1 << 5) + i0] =
                    make_float2(acc[st][nt][2], acc[st][nt][3]);
            }
        }
    }
}

extern "C" void kernel_launch(void* const* d_in, const int* in_sizes, int n_in,
                              void* d_out, int out_size)
{
    const float* x  = (const float*)d_in[0];
    const float* w0 = (const float*)d_in[1];
    const float* w1 = (const float*)d_in[2];
    const float* w2 = (const float*)d_in[3];
    float* out = (float*)d_out;

    const int nBatch = in_sizes[0] >> 15;
    const int grid = nBatch * 4;

    float* scratch;
    cudaGetSymbolAddress((void**)&scratch, g_scratch);

    stage_kernel<<<grid, 256>>>(x,       w0, out);      // x       -> out
    stage_kernel<<<grid, 256>>>(out,     w1, scratch);  // out     -> scratch
    stage_kernel<<<grid, 256>>>(scratch, w2, out);      // scratch -> out
}

// round 10
// speedup vs baseline: 1.3228x; 1.1278x over previous
#include <cuda_runtime.h>
#include <cstdint>

// 3-stage Tucker transform: three streaming GEMM launches, chunk-interleaved
// for L2 reuse. Stage: out[b, m*32+i] = sum_c in[b, c*1024+m] * w[c,i].
// Chain per chunk: x -> d_out -> scratch -> d_out.
// Numerics (proven R9, rel_err 7.6e-6): bf16 two-plane split on mma.sync
// m16n8k16: b0*B0 + b0*B1 + b1*B0.
// Round 10: A tile stored as two bf16 planes in smem (split done in fill),
// mainloop fragments via ldmatrix.x4; row stride 20 words + chunk-XOR
// swizzle (c4 ^ ((m>>3)&3)) => fill STS.128 and ldmatrix both conflict-free.

#define AST 20                       // words per row per plane (16 data + 4 pad)

__device__ float g_scratch[32 * 1024 * 1024];   // 128 MB inter-stage buffer

__device__ __forceinline__ uint32_t packbf(float hi, float lo) {
    uint32_t r;
    asm("cvt.rn.bf16x2.f32 %0, %1, %2;" : "=r"(r) : "f"(hi), "f"(lo));
    return r;
}

// v = plane0 + plane1 per lane; u = bf16x2(hi,lo), w = residual bf16x2.
__device__ __forceinline__ void split2(float vhi, float vlo, uint32_t& u, uint32_t& w) {
    u = packbf(vhi, vlo);
    float rlo = vlo - __uint_as_float(u << 16);
    float rhi = vhi - __uint_as_float(u & 0xFFFF0000u);
    w = packbf(rhi, rlo);
}

__device__ __forceinline__ void mma16(float* d, const uint32_t* a, uint32_t b0, uint32_t b1) {
    asm volatile(
        "mma.sync.aligned.m16n8k16.row.col.f32.bf16.bf16.f32 "
        "{%0,%1,%2,%3}, {%4,%5,%6,%7}, {%8,%9}, {%0,%1,%2,%3};"
        : "+f"(d[0]), "+f"(d[1]), "+f"(d[2]), "+f"(d[3])
        : "r"(a[0]), "r"(a[1]), "r"(a[2]), "r"(a[3]), "r"(b0), "r"(b1));
}

__device__ __forceinline__ void ldm4(uint32_t* a, uint32_t saddr) {
    asm volatile("ldmatrix.sync.aligned.m8n8.x4.shared.b16 {%0,%1,%2,%3}, [%4];"
        : "=r"(a[0]), "=r"(a[1]), "=r"(a[2]), "=r"(a[3]) : "r"(saddr));
}

template<bool STREAM>
__global__ __launch_bounds__(256)
void stage_v2(const float* __restrict__ in,
              const float* __restrict__ w,
              float* __restrict__ out,
              int batchOfs)
{
    __shared__ uint32_t A0[256 * AST];      // plane0 bf16x2 words
    __shared__ uint32_t A1[256 * AST];      // plane1
    __shared__ uint32_t Wb[2][640];         // packed weights [plane][n*20 + k2]

    const int tid  = threadIdx.x;
    const int wid  = tid >> 5;
    const int lane = tid & 31;
    const int g    = lane >> 2;
    const int tig  = lane & 3;

    const int b  = batchOfs + (blockIdx.x >> 2);
    const int mb = (blockIdx.x & 3) << 8;
    const long bb = (long)b << 15;

    // ---- Weight prep: split into two bf16x2 planes (k-pairs packed). ----
    #pragma unroll
    for (int e = tid; e < 512; e += 256) {
        int n = e & 31, k2 = e >> 5;
        float lo = w[(2 * k2) * 32 + n];
        float hi = w[(2 * k2 + 1) * 32 + n];
        uint32_t p, q;
        split2(hi, lo, p, q);
        Wb[0][n * 20 + k2] = p;
        Wb[1][n * 20 + k2] = q;
    }

    // ---- Fill: thread = row m (tid); split fp32 -> two bf16 planes. ----
    {
        const float* inb = in + bb + mb;
        const int physBase = tid * AST;
        const int sw = (tid >> 3) & 3;
        #pragma unroll
        for (int c4 = 0; c4 < 4; c4++) {
            uint32_t pa[4], pb[4];
            #pragma unroll
            for (int j = 0; j < 4; j++) {
                int c2 = c4 * 4 + j;
                float lo = inb[(2 * c2) * 1024 + tid];
                float hi = inb[(2 * c2 + 1) * 1024 + tid];
                split2(hi, lo, pa[j], pb[j]);
            }
            int phys = physBase + 4 * (c4 ^ sw);
            *(uint4*)&A0[phys] = make_uint4(pa[0], pa[1], pa[2], pa[3]);
            *(uint4*)&A1[phys] = make_uint4(pb[0], pb[1], pb[2], pb[3]);
        }
    }
    __syncthreads();

    // ---- Mainloop: per warp 32 m-rows (2 m16 strips), N=32, K=32. ----
    float acc[2][4][4];
    #pragma unroll
    for (int a = 0; a < 2; a++)
        #pragma unroll
        for (int n = 0; n < 4; n++)
            #pragma unroll
            for (int q = 0; q < 4; q++)
                acc[a][n][q] = 0.0f;

    const uint32_t a0b = (uint32_t)__cvta_generic_to_shared(A0);
    const uint32_t a1b = (uint32_t)__cvta_generic_to_shared(A1);
    // ldmatrix lane row/chunk: matrices (m0-7,k0-7),(m8-15,k0-7),(m0-7,k8-15),(m8-15,k8-15)
    const int lrow = (lane & 7) + ((lane >> 3) & 1) * 8;   // row within strip
    const int lck  = lane >> 4;                            // k8-block within k16

    #pragma unroll
    for (int ks = 0; ks < 2; ks++) {
        uint32_t ua[2][4], va[2][4];
        #pragma unroll
        for (int st = 0; st < 2; st++) {
            int r  = (wid << 5) + (st << 4) + lrow;
            int c4 = 2 * ks + lck;
            uint32_t word = r * AST + 4 * (c4 ^ ((r >> 3) & 3));
            ldm4(ua[st], a0b + word * 4);
            ldm4(va[st], a1b + word * 4);
        }
        #pragma unroll
        for (int nt = 0; nt < 4; nt++) {
            int wo = (nt * 8 + g) * 20 + (ks << 3) + tig;
            uint32_t b00 = Wb[0][wo], b01 = Wb[0][wo + 4];
            uint32_t b10 = Wb[1][wo], b11 = Wb[1][wo + 4];
            mma16(acc[0][nt], ua[0], b00, b01);   // b0*B0
            mma16(acc[1][nt], ua[1], b00, b01);
            mma16(acc[0][nt], ua[0], b10, b11);   // b0*B1
            mma16(acc[1][nt], ua[1], b10, b11);
            mma16(acc[0][nt], va[0], b00, b01);   // b1*B0
            mma16(acc[1][nt], va[1], b00, b01);
        }
    }

    // ---- Epilogue: out[b, (mb+m)*32 + i], float2 per (row, n-tile). ----
    {
        float* ob = out + bb + (long)mb * 32;
        #pragma unroll
        for (int st = 0; st < 2; st++) {
            int m0 = (wid << 5) + (st << 4) + g;
            int m1 = m0 + 8;
            #pragma unroll
            for (int nt = 0; nt < 4; nt++) {
                int i0 = (nt << 3) + (tig << 1);
                float2 v0 = make_float2(acc[st][nt][0], acc[st][nt][1]);
                float2 v1 = make_float2(acc[st][nt][2], acc[st][nt][3]);
                if (STREAM) {
                    __stwt((float2*)&ob[(m0 << 5) + i0], v0);
                    __stwt((float2*)&ob[(m1 << 5) + i0], v1);
                } else {
                    *(float2*)&ob[(m0 << 5) + i0] = v0;
                    *(float2*)&ob[(m1 << 5) + i0] = v1;
                }
            }
        }
    }
}

extern "C" void kernel_launch(void* const* d_in, const int* in_sizes, int n_in,
                              void* d_out, int out_size)
{
    const float* x  = (const float*)d_in[0];
    const float* w0 = (const float*)d_in[1];
    const float* w1 = (const float*)d_in[2];
    const float* w2 = (const float*)d_in[3];
    float* out = (float*)d_out;

    const int nBatch = in_sizes[0] >> 15;

    float* scratch;
    cudaGetSymbolAddress((void**)&scratch, g_scratch);

    // Chunked chaining: consumer launch immediately follows its producer so
    // the 64 MB intermediate chunk is still L2-resident.
    const int NC = (nBatch % 2 == 0) ? 2 : 1;
    const int bc = nBatch / NC;
    const int grid = bc * 4;

    for (int c = 0; c < NC; c++) {
        const int ofs = c * bc;
        stage_v2<false><<<grid, 256>>>(x,       w0, out,     ofs);
        stage_v2<false><<<grid, 256>>>(out,     w1, scratch, ofs);
        stage_v2<true ><<<grid, 256>>>(scratch, w2, out,     ofs);
    }
}

// round 11
// speedup vs baseline: 1.3922x; 1.0525x over previous
#include <cuda_runtime.h>
#include <cstdint>

// Single-launch 3-stage Tucker transform. Cluster of 4 CTAs = one batch
// element (32*32*32 fp32). Stage: out[b, m*32+i] = sum_c in[b, c*1024+m]*w[c,i].
// Stages chain through gmem (x -> out -> scratch -> out), but the exchange is
// cluster-internal (128 KB, just-written => L2-hot) and synchronized with
// threadfence + barrier.cluster instead of kernel boundaries.
// Numerics (proven, rel_err 7.6e-6): bf16 two-plane split on mma.sync
// m16n8k16, terms b0*B0 + b0*B1 + b1*B0; A tile as two bf16 planes in smem,
// fragments via ldmatrix.x4; stride-20 rows + chunk-XOR swizzle (conflict-free).

#define AST 20                       // words per row per plane (16 data + 4 pad)

__device__ float g_scratch[32 * 1024 * 1024];   // 128 MB inter-stage buffer

__device__ __forceinline__ uint32_t packbf(float hi, float lo) {
    uint32_t r;
    asm("cvt.rn.bf16x2.f32 %0, %1, %2;" : "=r"(r) : "f"(hi), "f"(lo));
    return r;
}

__device__ __forceinline__ void split2(float vhi, float vlo, uint32_t& u, uint32_t& w) {
    u = packbf(vhi, vlo);
    float rlo = vlo - __uint_as_float(u << 16);
    float rhi = vhi - __uint_as_float(u & 0xFFFF0000u);
    w = packbf(rhi, rlo);
}

__device__ __forceinline__ void mma16(float* d, const uint32_t* a, uint32_t b0, uint32_t b1) {
    asm volatile(
        "mma.sync.aligned.m16n8k16.row.col.f32.bf16.bf16.f32 "
        "{%0,%1,%2,%3}, {%4,%5,%6,%7}, {%8,%9}, {%0,%1,%2,%3};"
        : "+f"(d[0]), "+f"(d[1]), "+f"(d[2]), "+f"(d[3])
        : "r"(a[0]), "r"(a[1]), "r"(a[2]), "r"(a[3]), "r"(b0), "r"(b1));
}

__device__ __forceinline__ void ldm4(uint32_t* a, uint32_t saddr) {
    asm volatile("ldmatrix.sync.aligned.m8n8.x4.shared.b16 {%0,%1,%2,%3}, [%4];"
        : "=r"(a[0]), "=r"(a[1]), "=r"(a[2]), "=r"(a[3]) : "r"(saddr));
}

__global__ void __cluster_dims__(4, 1, 1) __launch_bounds__(256, 4)
tucker_cluster(const float* __restrict__ x,
               const float* __restrict__ w0,
               const float* __restrict__ w1,
               const float* __restrict__ w2,
               float* __restrict__ out,
               float* __restrict__ scr)
{
    __shared__ uint32_t A0[256 * AST];      // plane0 bf16x2 words
    __shared__ uint32_t A1[256 * AST];      // plane1
    __shared__ uint32_t Wb[2][640];         // packed weights [plane][n*20 + k2]

    const int tid  = threadIdx.x;
    const int wid  = tid >> 5;
    const int lane = tid & 31;
    const int g    = lane >> 2;
    const int tig  = lane & 3;

    const int p  = blockIdx.x & 3;          // cluster rank = m-block
    const int b  = blockIdx.x >> 2;         // batch element
    const int mb = p << 8;
    const long bb = (long)b << 15;

    const uint32_t a0b = (uint32_t)__cvta_generic_to_shared(A0);
    const uint32_t a1b = (uint32_t)__cvta_generic_to_shared(A1);
    const int lrow = (lane & 7) + ((lane >> 3) & 1) * 8;
    const int lck  = lane >> 4;

    const float* src = x;
    float* dst = out;

    #pragma unroll 1
    for (int s = 0; s < 3; s++) {
        const float* w = (s == 0) ? w0 : (s == 1) ? w1 : w2;

        // ---- Weight prep: split into two bf16x2 planes (k-pairs packed). ----
        #pragma unroll
        for (int e = tid; e < 512; e += 256) {
            int n = e & 31, k2 = e >> 5;
            float lo = w[(2 * k2) * 32 + n];
            float hi = w[(2 * k2 + 1) * 32 + n];
            uint32_t pq, qq;
            split2(hi, lo, pq, qq);
            Wb[0][n * 20 + k2] = pq;
            Wb[1][n * 20 + k2] = qq;
        }

        // ---- Fill: thread = row m (tid); split fp32 -> two bf16 planes. ----
        // L2-direct loads: exchange data is stream-once and (for s>=1) was
        // written by peer CTAs -- bypassing L1 also guarantees freshness.
        {
            const float* inb = src + bb + mb;
            const int physBase = tid * AST;
            const int sw = (tid >> 3) & 3;
            #pragma unroll
            for (int c4 = 0; c4 < 4; c4++) {
                uint32_t pa[4], pb[4];
                #pragma unroll
                for (int j = 0; j < 4; j++) {
                    int c2 = c4 * 4 + j;
                    float lo = __ldcg(&inb[(2 * c2) * 1024 + tid]);
                    float hi = __ldcg(&inb[(2 * c2 + 1) * 1024 + tid]);
                    split2(hi, lo, pa[j], pb[j]);
                }
                int phys = physBase + 4 * (c4 ^ sw);
                *(uint4*)&A0[phys] = make_uint4(pa[0], pa[1], pa[2], pa[3]);
                *(uint4*)&A1[phys] = make_uint4(pb[0], pb[1], pb[2], pb[3]);
            }
        }
        __syncthreads();

        // ---- Mainloop: per warp 32 m-rows (2 m16 strips), N=32, K=32. ----
        float acc[2][4][4];
        #pragma unroll
        for (int a = 0; a < 2; a++)
            #pragma unroll
            for (int n = 0; n < 4; n++)
                #pragma unroll
                for (int q = 0; q < 4; q++)
                    acc[a][n][q] = 0.0f;

        #pragma unroll
        for (int ks = 0; ks < 2; ks++) {
            uint32_t ua[2][4], va[2][4];
            #pragma unroll
            for (int st = 0; st < 2; st++) {
                int r  = (wid << 5) + (st << 4) + lrow;
                int c4 = 2 * ks + lck;
                uint32_t word = r * AST + 4 * (c4 ^ ((r >> 3) & 3));
                ldm4(ua[st], a0b + word * 4);
                ldm4(va[st], a1b + word * 4);
            }
            #pragma unroll
            for (int nt = 0; nt < 4; nt++) {
                int wo = (nt * 8 + g) * 20 + (ks << 3) + tig;
                uint32_t b00 = Wb[0][wo], b01 = Wb[0][wo + 4];
                uint32_t b10 = Wb[1][wo], b11 = Wb[1][wo + 4];
                mma16(acc[0][nt], ua[0], b00, b01);   // b0*B0
                mma16(acc[1][nt], ua[1], b00, b01);
                mma16(acc[0][nt], ua[0], b10, b11);   // b0*B1
                mma16(acc[1][nt], ua[1], b10, b11);
                mma16(acc[0][nt], va[0], b00, b01);   // b1*B0
                mma16(acc[1][nt], va[1], b00, b01);
            }
        }

        // ---- Epilogue: dst[b, (mb+m)*32 + i]. Final stage streams (stwt). ----
        {
            float* ob = dst + bb + (long)mb * 32;
            #pragma unroll
            for (int st = 0; st < 2; st++) {
                int m0 = (wid << 5) + (st << 4) + g;
                int m1 = m0 + 8;
                #pragma unroll
                for (int nt = 0; nt < 4; nt++) {
                    int i0 = (nt << 3) + (tig << 1);
                    float2 v0 = make_float2(acc[st][nt][0], acc[st][nt][1]);
                    float2 v1 = make_float2(acc[st][nt][2], acc[st][nt][3]);
                    if (s == 2) {
                        __stwt((float2*)&ob[(m0 << 5) + i0], v0);
                        __stwt((float2*)&ob[(m1 << 5) + i0], v1);
                    } else {
                        *(float2*)&ob[(m0 << 5) + i0] = v0;
                        *(float2*)&ob[(m1 << 5) + i0] = v1;
                    }
                }
            }
        }

        if (s < 2) {
            // Release our slab to the cluster, wait for siblings' slabs.
            __threadfence();
            asm volatile("barrier.cluster.arrive.aligned;" ::: "memory");
            asm volatile("barrier.cluster.wait.aligned;" ::: "memory");
        }

        src = dst;
        dst = (s == 0) ? scr : out;
    }
}

extern "C" void kernel_launch(void* const* d_in, const int* in_sizes, int n_in,
                              void* d_out, int out_size)
{
    const float* x  = (const float*)d_in[0];
    const float* w0 = (const float*)d_in[1];
    const float* w1 = (const float*)d_in[2];
    const float* w2 = (const float*)d_in[3];
    float* out = (float*)d_out;

    const int nBatch = in_sizes[0] >> 15;
    const int grid = nBatch * 4;            // cluster (4,1,1) per batch

    float* scratch;
    cudaGetSymbolAddress((void**)&scratch, g_scratch);

    tucker_cluster<<<grid, 256>>>(x, w0, w1, w2, out, scratch);
}

// round 12
// speedup vs baseline: 1.4140x; 1.0156x over previous
#include <cuda_runtime.h>
#include <cstdint>

// Single-launch 3-stage Tucker transform, cluster of 4 CTAs = one batch
// element. Inter-stage exchange goes DIRECTLY through peer shared memory
// (st.shared::cluster): producer warps split to bf16 planes and write into
// the consumer CTA's K-major A tile. No gmem round trip between stages.
//
// Stage GEMM: out[m,i] = sum_c A[m,c]*w[c,i]. A stored K-major: AT[c][m'],
// 32 rows x 256 bf16 per plane, fragments via ldmatrix.x4.trans.
// Granule swizzle: phys_gm = F(gm) ^ (k&7), F(gm)=((gm&3)<<3)|(gm>>2).
//   - ldmatrix reads: conflict-free (XOR k distributes k-rows)
//   - DSMEM column writes: F makes granule bank-group = g -> conflict-free
//   - stage-0 fill STS: bandwidth-minimal
// Numerics (proven, rel_err 7.6e-6): bf16 two-plane split on mma m16n8k16,
// terms b0*B0 + b0*B1 + b1*B0.

#define PLANE_WORDS 4096           // 32 k-rows * 128 words (512 B/row)
#define PLANE_BYTES 16384
#define ABUF_WORDS  8192           // 2 planes
#define WB_OFS      16384          // after 2 A buffers (words)
#define SMEM_BYTES  ((WB_OFS + 1280) * 4)   // 70656 B

__device__ __forceinline__ uint32_t packbf(float hi, float lo) {
    uint32_t r;
    asm("cvt.rn.bf16x2.f32 %0, %1, %2;" : "=r"(r) : "f"(hi), "f"(lo));
    return r;
}
__device__ __forceinline__ void split2(float vhi, float vlo, uint32_t& u, uint32_t& w) {
    u = packbf(vhi, vlo);
    float rlo = vlo - __uint_as_float(u << 16);
    float rhi = vhi - __uint_as_float(u & 0xFFFF0000u);
    w = packbf(rhi, rlo);
}
__device__ __forceinline__ void mma16(float* d, const uint32_t* a, uint32_t b0, uint32_t b1) {
    asm volatile(
        "mma.sync.aligned.m16n8k16.row.col.f32.bf16.bf16.f32 "
        "{%0,%1,%2,%3}, {%4,%5,%6,%7}, {%8,%9}, {%0,%1,%2,%3};"
        : "+f"(d[0]), "+f"(d[1]), "+f"(d[2]), "+f"(d[3])
        : "r"(a[0]), "r"(a[1]), "r"(a[2]), "r"(a[3]), "r"(b0), "r"(b1));
}
__device__ __forceinline__ void ldm4t(uint32_t* a, uint32_t saddr) {
    asm volatile("ldmatrix.sync.aligned.m8n8.x4.trans.shared.b16 {%0,%1,%2,%3}, [%4];"
        : "=r"(a[0]), "=r"(a[1]), "=r"(a[2]), "=r"(a[3]) : "r"(saddr));
}
__device__ __forceinline__ uint32_t Fgm(uint32_t gm) {
    return ((gm & 3u) << 3) | (gm >> 2);
}
__device__ __forceinline__ void stcluster(uint32_t addr, uint32_t v) {
    asm volatile("st.shared::cluster.b32 [%0], %1;" :: "r"(addr), "r"(v) : "memory");
}

__global__ void __cluster_dims__(4, 1, 1) __launch_bounds__(256, 3)
tucker_dsmem(const float* __restrict__ x,
             const float* __restrict__ w0,
             const float* __restrict__ w1,
             const float* __restrict__ w2,
             float* __restrict__ out)
{
    extern __shared__ uint32_t smem[];
    uint32_t* Wb0 = smem + WB_OFS;          // 640 words per plane
    uint32_t* Wb1 = Wb0 + 640;

    const int tid  = threadIdx.x;
    const int wid  = tid >> 5;
    const int lane = tid & 31;
    const int g    = lane >> 2;
    const int tig  = lane & 3;

    const int rank = blockIdx.x & 3;
    const int b    = blockIdx.x >> 2;
    const int mb   = rank << 8;
    const long bb  = (long)b << 15;

    const uint32_t smemBase = (uint32_t)__cvta_generic_to_shared(smem);

    // ---- Stage-0 fill: x is already K-major (row c = contiguous m). ----
    {
        #pragma unroll
        for (int rr = 0; rr < 4; rr++) {
            const int k = wid * 4 + rr;
            const float4* src = (const float4*)(x + bb + (long)k * 1024 + mb + lane * 8);
            float4 f0 = __ldcg(src);
            float4 f1 = __ldcg(src + 1);
            uint32_t p0[4], p1[4];
            split2(f0.y, f0.x, p0[0], p1[0]);
            split2(f0.w, f0.z, p0[1], p1[1]);
            split2(f1.y, f1.x, p0[2], p1[2]);
            split2(f1.w, f1.z, p0[3], p1[3]);
            uint32_t wofs = k * 128 + (Fgm(lane) ^ (k & 7)) * 4;  // buf0 plane0
            *(uint4*)&smem[wofs]               = make_uint4(p0[0], p0[1], p0[2], p0[3]);
            *(uint4*)&smem[wofs + PLANE_WORDS] = make_uint4(p1[0], p1[1], p1[2], p1[3]);
        }
    }

    #pragma unroll 1
    for (int s = 0; s < 3; s++) {
        const float* w = (s == 0) ? w0 : (s == 1) ? w1 : w2;
        const int bufR = s & 1;                 // 0,1,0
        const int bufW = 1 - bufR;

        // ---- Weight prep: split into two bf16x2 planes (k-pairs packed). ----
        #pragma unroll
        for (int e = tid; e < 512; e += 256) {
            int n = e & 31, k2 = e >> 5;
            float lo = w[(2 * k2) * 32 + n];
            float hi = w[(2 * k2 + 1) * 32 + n];
            uint32_t pq, qq;
            split2(hi, lo, pq, qq);
            Wb0[n * 20 + k2] = pq;
            Wb1[n * 20 + k2] = qq;
        }
        __syncthreads();                        // fill/weights visible CTA-wide

        // ---- Mainloop: ldmatrix.trans fragments from K-major A planes. ----
        const uint32_t aR0 = smemBase + bufR * (ABUF_WORDS * 4);
        const uint32_t aR1 = aR0 + PLANE_BYTES;

        float acc[2][4][4];
        #pragma unroll
        for (int a = 0; a < 2; a++)
            #pragma unroll
            for (int n = 0; n < 4; n++)
                #pragma unroll
                for (int q = 0; q < 4; q++)
                    acc[a][n][q] = 0.0f;

        #pragma unroll
        for (int ks = 0; ks < 2; ks++) {
            uint32_t ua[2][4], va[2][4];
            #pragma unroll
            for (int st = 0; st < 2; st++) {
                int klane = ks * 16 + ((lane >> 4) << 3) + (lane & 7);
                int gm    = 4 * wid + 2 * st + ((lane >> 3) & 1);
                uint32_t boff = klane * 512 + (Fgm(gm) ^ (klane & 7)) * 16;
                ldm4t(ua[st], aR0 + boff);
                ldm4t(va[st], aR1 + boff);
            }
            #pragma unroll
            for (int nt = 0; nt < 4; nt++) {
                int wo = (nt * 8 + g) * 20 + (ks << 3) + tig;
                uint32_t b00 = Wb0[wo], b01 = Wb0[wo + 4];
                uint32_t b10 = Wb1[wo], b11 = Wb1[wo + 4];
                mma16(acc[0][nt], ua[0], b00, b01);   // b0*B0
                mma16(acc[1][nt], ua[1], b00, b01);
                mma16(acc[0][nt], ua[0], b10, b11);   // b0*B1
                mma16(acc[1][nt], ua[1], b10, b11);
                mma16(acc[0][nt], va[0], b00, b01);   // b1*B0
                mma16(acc[1][nt], va[1], b00, b01);
            }
        }

        if (s < 2) {
            // ---- DSMEM epilogue: warp owns column c' = 8*rank + wid.
            // Consumer p' <- strip (st = p'>>1) half (mh = p'&1); within it
            // m'_local = g*32 + 8nt + 2tig (+1), i.e. word gm_w = 4g + nt.
            const int cp = 8 * rank + wid;
            const uint32_t locPlane0 =
                smemBase + bufW * (ABUF_WORDS * 4) + cp * 512;
            #pragma unroll
            for (int pc = 0; pc < 4; pc++) {
                uint32_t rem;
                asm("mapa.shared::cluster.u32 %0, %1, %2;"
                    : "=r"(rem) : "r"(locPlane0), "r"(pc));
                const int st = pc >> 1, mh = pc & 1;
                #pragma unroll
                for (int nt = 0; nt < 4; nt++) {
                    uint32_t u, v;
                    split2(acc[st][nt][2 * mh + 1], acc[st][nt][2 * mh], u, v);
                    uint32_t gmw = 4 * g + nt;
                    uint32_t off = (Fgm(gmw) ^ (cp & 7)) * 16 + tig * 4;
                    stcluster(rem + off, u);
                    stcluster(rem + off + PLANE_BYTES, v);
                }
            }
            // Release our writes to the cluster; wait for all peers.
            asm volatile("barrier.cluster.arrive.aligned;" ::: "memory");
            asm volatile("barrier.cluster.wait.aligned;" ::: "memory");
        } else {
            // ---- Final stage: stream to gmem, out flat = (mb+m)*32 + i. ----
            float* ob = out + bb + (long)mb * 32;
            #pragma unroll
            for (int st = 0; st < 2; st++) {
                int m0 = (wid << 5) + (st << 4) + g;
                int m1 = m0 + 8;
                #pragma unroll
                for (int nt = 0; nt < 4; nt++) {
                    int i0 = (nt << 3) + (tig << 1);
                    __stwt((float2*)&ob[(m0 << 5) + i0],
                           make_float2(acc[st][nt][0], acc[st][nt][1]));
                    __stwt((float2*)&ob[(m1 << 5) + i0],
                           make_float2(acc[st][nt][2], acc[st][nt][3]));
                }
            }
        }
    }
}

extern "C" void kernel_launch(void* const* d_in, const int* in_sizes, int n_in,
                              void* d_out, int out_size)
{
    const float* x  = (const float*)d_in[0];
    const float* w0 = (const float*)d_in[1];
    const float* w1 = (const float*)d_in[2];
    const float* w2 = (const float*)d_in[3];
    float* out = (float*)d_out;

    const int nBatch = in_sizes[0] >> 15;
    const int grid = nBatch * 4;            // cluster (4,1,1) per batch

    cudaFuncSetAttribute(tucker_dsmem,
                         cudaFuncAttributeMaxDynamicSharedMemorySize, SMEM_BYTES);
    tucker_dsmem<<<grid, 256, SMEM_BYTES>>>(x, w0, w1, w2, out);
}

// round 13
// speedup vs baseline: 1.5808x; 1.1180x over previous
#include <cuda_runtime.h>
#include <cstdint>

// Single-launch 3-stage Tucker transform, cluster of 4 CTAs = one batch.
// Inter-stage exchange via st.shared::cluster into the consumer's K-major
// bf16-plane A tile (no gmem round trip). Round 13: single A buffer +
// read-done/write-done cluster barrier pair, all-stage weight prep hoisted,
// launch_bounds(256,4) -> 64 regs, 48 KB smem => 4 CTAs/SM.
//
// Stage GEMM: out[m,i] = sum_c A[m,c]*w[c,i]. A K-major: AT[c][m'], 32 rows
// x 256 bf16 per plane, fragments via ldmatrix.x4.trans.
// Granule swizzle: phys_gm = F(gm) ^ (k&7), F(gm)=((gm&3)<<3)|(gm>>2):
// ldmatrix reads, DSMEM column writes, and fill STS all conflict-free.
// Numerics (proven, rel_err 7.6e-6): bf16 two-plane split on mma m16n8k16,
// terms b0*B0 + b0*B1 + b1*B0.

#define PLANE_WORDS 4096           // 32 k-rows * 128 words (512 B/row)
#define PLANE_BYTES 16384
#define W_OFS       8192           // words: after single A buffer (2 planes)
#define SMEM_BYTES  ((W_OFS + 3 * 1280) * 4)   // 48128 B

__device__ __forceinline__ uint32_t packbf(float hi, float lo) {
    uint32_t r;
    asm("cvt.rn.bf16x2.f32 %0, %1, %2;" : "=r"(r) : "f"(hi), "f"(lo));
    return r;
}
__device__ __forceinline__ void split2(float vhi, float vlo, uint32_t& u, uint32_t& w) {
    u = packbf(vhi, vlo);
    float rlo = vlo - __uint_as_float(u << 16);
    float rhi = vhi - __uint_as_float(u & 0xFFFF0000u);
    w = packbf(rhi, rlo);
}
__device__ __forceinline__ void mma16(float* d, const uint32_t* a, uint32_t b0, uint32_t b1) {
    asm volatile(
        "mma.sync.aligned.m16n8k16.row.col.f32.bf16.bf16.f32 "
        "{%0,%1,%2,%3}, {%4,%5,%6,%7}, {%8,%9}, {%0,%1,%2,%3};"
        : "+f"(d[0]), "+f"(d[1]), "+f"(d[2]), "+f"(d[3])
        : "r"(a[0]), "r"(a[1]), "r"(a[2]), "r"(a[3]), "r"(b0), "r"(b1));
}
__device__ __forceinline__ void ldm4t(uint32_t* a, uint32_t saddr) {
    asm volatile("ldmatrix.sync.aligned.m8n8.x4.trans.shared.b16 {%0,%1,%2,%3}, [%4];"
        : "=r"(a[0]), "=r"(a[1]), "=r"(a[2]), "=r"(a[3]) : "r"(saddr));
}
__device__ __forceinline__ uint32_t Fgm(uint32_t gm) {
    return ((gm & 3u) << 3) | (gm >> 2);
}
__device__ __forceinline__ void stcluster(uint32_t addr, uint32_t v) {
    asm volatile("st.shared::cluster.b32 [%0], %1;" :: "r"(addr), "r"(v) : "memory");
}
__device__ __forceinline__ void cbar() {
    asm volatile("barrier.cluster.arrive.aligned;" ::: "memory");
    asm volatile("barrier.cluster.wait.aligned;" ::: "memory");
}

__global__ void __cluster_dims__(4, 1, 1) __launch_bounds__(256, 4)
tucker_dsmem(const float* __restrict__ x,
             const float* __restrict__ w0,
             const float* __restrict__ w1,
             const float* __restrict__ w2,
             float* __restrict__ out)
{
    extern __shared__ uint32_t smem[];

    const int tid  = threadIdx.x;
    const int wid  = tid >> 5;
    const int lane = tid & 31;
    const int g    = lane >> 2;
    const int tig  = lane & 3;

    const int rank = blockIdx.x & 3;
    const int b    = blockIdx.x >> 2;
    const int mb   = rank << 8;
    const long bb  = (long)b << 15;

    const uint32_t smemBase = (uint32_t)__cvta_generic_to_shared(smem);

    // ---- One-time weight prep: all 3 stages, two bf16x2 planes each. ----
    {
        const float* ws[3] = {w0, w1, w2};
        #pragma unroll
        for (int s3 = 0; s3 < 3; s3++) {
            uint32_t* Wb0 = smem + W_OFS + s3 * 1280;
            #pragma unroll
            for (int e = tid; e < 512; e += 256) {
                int n = e & 31, k2 = e >> 5;
                float lo = ws[s3][(2 * k2) * 32 + n];
                float hi = ws[s3][(2 * k2 + 1) * 32 + n];
                uint32_t pq, qq;
                split2(hi, lo, pq, qq);
                Wb0[n * 20 + k2]       = pq;
                Wb0[640 + n * 20 + k2] = qq;
            }
        }
    }

    // ---- Stage-0 fill: x is already K-major (row c = contiguous m). ----
    {
        #pragma unroll
        for (int rr = 0; rr < 4; rr++) {
            const int k = wid * 4 + rr;
            const float4* src = (const float4*)(x + bb + (long)k * 1024 + mb + lane * 8);
            float4 f0 = __ldcg(src);
            float4 f1 = __ldcg(src + 1);
            uint32_t p0[4], p1[4];
            split2(f0.y, f0.x, p0[0], p1[0]);
            split2(f0.w, f0.z, p0[1], p1[1]);
            split2(f1.y, f1.x, p0[2], p1[2]);
            split2(f1.w, f1.z, p0[3], p1[3]);
            uint32_t wofs = k * 128 + (Fgm(lane) ^ (k & 7)) * 4;
            *(uint4*)&smem[wofs]               = make_uint4(p0[0], p0[1], p0[2], p0[3]);
            *(uint4*)&smem[wofs + PLANE_WORDS] = make_uint4(p1[0], p1[1], p1[2], p1[3]);
        }
    }
    __syncthreads();

    #pragma unroll 1
    for (int s = 0; s < 3; s++) {
        const uint32_t* Wb0 = smem + W_OFS + s * 1280;
        const uint32_t* Wb1 = Wb0 + 640;

        // ---- Mainloop: ldmatrix.trans fragments from K-major A planes. ----
        float acc[2][4][4];
        #pragma unroll
        for (int a = 0; a < 2; a++)
            #pragma unroll
            for (int n = 0; n < 4; n++)
                #pragma unroll
                for (int q = 0; q < 4; q++)
                    acc[a][n][q] = 0.0f;

        #pragma unroll
        for (int ks = 0; ks < 2; ks++) {
            uint32_t ua[2][4], va[2][4];
            #pragma unroll
            for (int st = 0; st < 2; st++) {
                int klane = ks * 16 + ((lane >> 4) << 3) + (lane & 7);
                int gm    = 4 * wid + 2 * st + ((lane >> 3) & 1);
                uint32_t boff = klane * 512 + (Fgm(gm) ^ (klane & 7)) * 16;
                ldm4t(ua[st], smemBase + boff);
                ldm4t(va[st], smemBase + PLANE_BYTES + boff);
            }
            #pragma unroll
            for (int nt = 0; nt < 4; nt++) {
                int wo = (nt * 8 + g) * 20 + (ks << 3) + tig;
                uint32_t b00 = Wb0[wo], b01 = Wb0[wo + 4];
                uint32_t b10 = Wb1[wo], b11 = Wb1[wo + 4];
                mma16(acc[0][nt], ua[0], b00, b01);   // b0*B0
                mma16(acc[1][nt], ua[1], b00, b01);
                mma16(acc[0][nt], ua[0], b10, b11);   // b0*B1
                mma16(acc[1][nt], ua[1], b10, b11);
                mma16(acc[0][nt], va[0], b00, b01);   // b1*B0
                mma16(acc[1][nt], va[1], b00, b01);
            }
        }

        if (s < 2) {
            // Read-done: no peer may overwrite the (single) A buffer until
            // every cluster CTA finished its mainloop reads.
            cbar();

            // ---- DSMEM epilogue: warp owns column c' = 8*rank + wid. ----
            const int cp = 8 * rank + wid;
            const uint32_t locPlane0 = smemBase + cp * 512;
            #pragma unroll
            for (int pc = 0; pc < 4; pc++) {
                uint32_t rem;
                asm("mapa.shared::cluster.u32 %0, %1, %2;"
                    : "=r"(rem) : "r"(locPlane0), "r"(pc));
                const int st = pc >> 1, mh = pc & 1;
                #pragma unroll
                for (int nt = 0; nt < 4; nt++) {
                    uint32_t u, v;
                    split2(acc[st][nt][2 * mh + 1], acc[st][nt][2 * mh], u, v);
                    uint32_t gmw = 4 * g + nt;
                    uint32_t off = (Fgm(gmw) ^ (cp & 7)) * 16 + tig * 4;
                    stcluster(rem + off, u);
                    stcluster(rem + off + PLANE_BYTES, v);
                }
            }
            // Write-done: peers' tiles fully written before next mainloop.
            cbar();
        } else {
            // ---- Final stage: stream to gmem, out flat = (mb+m)*32 + i. ----
            float* ob = out + bb + (long)mb * 32;
            #pragma unroll
            for (int st = 0; st < 2; st++) {
                int m0 = (wid << 5) + (st << 4) + g;
                int m1 = m0 + 8;
                #pragma unroll
                for (int nt = 0; nt < 4; nt++) {
                    int i0 = (nt << 3) + (tig << 1);
                    __stwt((float2*)&ob[(m0 << 5) + i0],
                           make_float2(acc[st][nt][0], acc[st][nt][1]));
                    __stwt((float2*)&ob[(m1 << 5) + i0],
                           make_float2(acc[st][nt][2], acc[st][nt][3]));
                }
            }
        }
    }
}

extern "C" void kernel_launch(void* const* d_in, const int* in_sizes, int n_in,
                              void* d_out, int out_size)
{
    const float* x  = (const float*)d_in[0];
    const float* w0 = (const float*)d_in[1];
    const float* w1 = (const float*)d_in[2];
    const float* w2 = (const float*)d_in[3];
    float* out = (float*)d_out;

    const int nBatch = in_sizes[0] >> 15;
    const int grid = nBatch * 4;            // cluster (4,1,1) per batch

    cudaFuncSetAttribute(tucker_dsmem,
                         cudaFuncAttributeMaxDynamicSharedMemorySize, SMEM_BYTES);
    tucker_dsmem<<<grid, 256, SMEM_BYTES>>>(x, w0, w1, w2, out);
}